// round 8
// baseline (speedup 1.0000x reference)
#include <cuda_runtime.h>
#include <math.h>

// B=1024, T=128, H1=50 (G1=200), H2=150 (G2=600), D2=100
#define B_SZ 1024
#define T_SZ 128

// output: concat of flattened (waveform_feat[1024,20], pef_logits[1024,2],
//                              feat[1024,30], logits[1024,4])
#define OFF_WF   0
#define OFF_PL   20480
#define OFF_FEAT 22528
#define OFF_LG   53248

typedef unsigned long long ull;

static __device__ float  g_out1[(size_t)B_SZ * T_SZ * 100];   // layer1 output (52 MB)
static __device__ float  g_xg2 [(size_t)B_SZ * T_SZ * 600];   // layer2 fwd input proj (315 MB)
static __device__ float2 g_W2p [76 * 600];                    // layer2 fwd Whh, k-pair-major
static __device__ float  g_net [(size_t)B_SZ * 300];          // out2[:, -1]

// ---------------- fast math helpers ----------------
__device__ __forceinline__ float tanh_(float x) {
    float r; asm("tanh.approx.f32 %0, %1;" : "=f"(r) : "f"(x)); return r;
}
__device__ __forceinline__ float sigm(float x) {
    return fmaf(tanh_(0.5f * x), 0.5f, 0.5f);
}
__device__ __forceinline__ float lrelu(float x) { return x > 0.f ? x : 0.3f * x; }

__device__ __forceinline__ ull pack2(float lo, float hi) {
    ull r;
    asm("mov.b64 %0, {%1, %2};" : "=l"(r) : "r"(__float_as_uint(lo)), "r"(__float_as_uint(hi)));
    return r;
}
__device__ __forceinline__ void unpack2(ull v, float& lo, float& hi) {
    unsigned int a, b;
    asm("mov.b64 {%0, %1}, %2;" : "=r"(a), "=r"(b) : "l"(v));
    lo = __uint_as_float(a); hi = __uint_as_float(b);
}
__device__ __forceinline__ void fma2(ull& d, ull a, ull b) {
    asm("fma.rn.f32x2 %0, %1, %2, %3;" : "=l"(d) : "l"(a), "l"(b), "l"(d));
}

// ---------------------------------------------------------------------------
// prep: l2_Whh_f (600x150) -> g_W2p[k2][r] = (W[2k2][r], W[2k2+1][r]), k>=150 -> 0
// ---------------------------------------------------------------------------
__global__ void prep_kernel(const float* __restrict__ Whh2f)
{
    int i = blockIdx.x * 256 + threadIdx.x;
    if (i < 76 * 600) {
        int k2 = i / 600, r = i - k2 * 600;
        float lo = (2 * k2     < 150) ? Whh2f[r * 150 + 2 * k2]     : 0.f;
        float hi = (2 * k2 + 1 < 150) ? Whh2f[r * 150 + 2 * k2 + 1] : 0.f;
        g_W2p[i] = make_float2(lo, hi);
    }
}

// ---------------------------------------------------------------------------
// lstm1: grid (128, 2) = (batch groups of 8, direction), 256 threads.
// 256 CTAs -> ~2 CTAs/SM so barrier phases of neighbor CTAs interleave.
// ---------------------------------------------------------------------------
__global__ __launch_bounds__(256) void lstm1_kernel(
    const float* __restrict__ x,
    const float* __restrict__ Wih_f, const float* __restrict__ Whh_f, const float* __restrict__ b_f,
    const float* __restrict__ Wih_b, const float* __restrict__ Whh_b, const float* __restrict__ b_b)
{
    __shared__ __align__(16) float h_s[8 * 52];
    __shared__ float c_s[8 * 50];
    __shared__ float gates_s[8 * 200];
    __shared__ float x_s[8 * 128];

    const int tid = threadIdx.x;
    const int dir = blockIdx.y;
    const int b0  = blockIdx.x * 8;

    const float* Wih = dir ? Wih_b : Wih_f;
    const float* Whh = dir ? Whh_b : Whh_f;
    const float* bb  = dir ? b_b   : b_f;

    for (int i = tid; i < 8 * 128; i += 256) {
        int b = i >> 7, t = i & 127;
        x_s[i] = x[(size_t)(b0 + b) * 128 + t];
    }
    for (int i = tid; i < 8 * 52; i += 256) h_s[i] = 0.f;
    for (int i = tid; i < 8 * 50; i += 256) c_s[i] = 0.f;

    ull w2[26];
    float wih = 0.f, bv = 0.f;
    if (tid < 200) {
#pragma unroll
        for (int k2 = 0; k2 < 26; k2++) {
            float lo = (2 * k2     < 50) ? Whh[tid * 50 + 2 * k2]     : 0.f;
            float hi = (2 * k2 + 1 < 50) ? Whh[tid * 50 + 2 * k2 + 1] : 0.f;
            w2[k2] = pack2(lo, hi);
        }
        wih = Wih[tid];
        bv  = bb[tid];
    }
    __syncthreads();

    for (int s = 0; s < T_SZ; s++) {
        const int t = dir ? (127 - s) : s;
        if (tid < 200) {
#pragma unroll 2
            for (int b = 0; b < 8; b++) {
                ull acc = pack2(fmaf(x_s[b * 128 + t], wih, bv), 0.f);
#pragma unroll
                for (int k4 = 0; k4 < 13; k4++) {
                    ulonglong2 hv = *(const ulonglong2*)(h_s + b * 52 + k4 * 4);
                    fma2(acc, hv.x, w2[2 * k4]);
                    fma2(acc, hv.y, w2[2 * k4 + 1]);
                }
                float lo, hi; unpack2(acc, lo, hi);
                gates_s[b * 200 + tid] = lo + hi;
            }
        }
        __syncthreads();
        for (int p = tid; p < 8 * 50; p += 256) {
            int b = p / 50, j = p - b * 50;
            float gi = gates_s[b * 200 + j];
            float gf = gates_s[b * 200 + 50 + j];
            float gg = gates_s[b * 200 + 100 + j];
            float go = gates_s[b * 200 + 150 + j];
            float c = sigm(gf) * c_s[b * 50 + j] + sigm(gi) * tanh_(gg);
            c_s[b * 50 + j] = c;
            float h = sigm(go) * tanh_(c);
            h_s[b * 52 + j] = h;
            g_out1[(size_t)(b0 + b) * 12800 + (size_t)t * 100 + dir * 50 + j] = h;
        }
        __syncthreads();
    }
}

// ---------------------------------------------------------------------------
// xg2 GEMM: C[m][g] = out1[m][:100] . Wih2_f[g][:100] + b2_f[g]
// M = 131072, K = 100, N = 600.  BM=64, BN=64, 256 threads, 4x4 tiles.
// B stored pre-duplicated ((b,b) ulls) so inner loop = 3 LDS + 8 fma2, no ALU.
// smem: A_s 6800 floats (27.2 KB) + B2_s 6800 ulls (54.4 KB) = 81.6 KB dynamic
// ---------------------------------------------------------------------------
#define XG2_SMEM_BYTES (6800 * 4 + 6800 * 8)

extern __shared__ float xg2_sm[];

__global__ __launch_bounds__(256) void xg2_kernel(
    const float* __restrict__ W, const float* __restrict__ bias)
{
    float* A_s = xg2_sm;                      // [k*68 + m], 100 x 68
    ull*   B2_s = (ull*)(xg2_sm + 6800);      // [k*68 + n], 100 x 68, (b,b) dup

    const int m0 = blockIdx.x * 64;
    const int n0 = blockIdx.y * 64;
    const int tid = threadIdx.x;
    const int tx = tid & 15;   // n
    const int ty = tid >> 4;   // m

    // fill A (64 m x 100 k) and B2 (64 n x 100 k, duplicated)
    for (int i = tid; i < 6400; i += 256) {
        int mm = i / 100, kk = i - mm * 100;
        A_s[kk * 68 + mm] = g_out1[(size_t)(m0 + mm) * 100 + kk];
    }
    for (int i = tid; i < 6400; i += 256) {
        int nn = i / 100, kk = i - nn * 100;
        int g = n0 + nn;
        float v = (g < 600) ? W[g * 100 + kk] : 0.f;
        B2_s[kk * 68 + nn] = pack2(v, v);
    }
    __syncthreads();

    ull acc[2][4];   // [m-pair p][n] ; lo = row ty*4+2p, hi = row ty*4+2p+1
#pragma unroll
    for (int p = 0; p < 2; p++)
#pragma unroll
        for (int n = 0; n < 4; n++) acc[p][n] = pack2(0.f, 0.f);

#pragma unroll 10
    for (int k = 0; k < 100; k++) {
        ulonglong2 am  = *(const ulonglong2*)(A_s + k * 68 + ty * 4);      // (m0,m1),(m2,m3)
        ulonglong2 b01 = *(const ulonglong2*)(B2_s + k * 68 + tx * 4);     // splat n0, n1
        ulonglong2 b23 = *(const ulonglong2*)(B2_s + k * 68 + tx * 4 + 2); // splat n2, n3
        fma2(acc[0][0], am.x, b01.x); fma2(acc[0][1], am.x, b01.y);
        fma2(acc[0][2], am.x, b23.x); fma2(acc[0][3], am.x, b23.y);
        fma2(acc[1][0], am.y, b01.x); fma2(acc[1][1], am.y, b01.y);
        fma2(acc[1][2], am.y, b23.x); fma2(acc[1][3], am.y, b23.y);
    }

    const int nbase = n0 + tx * 4;
    if (nbase < 600) {
        float4 bb = *(const float4*)(bias + nbase);
#pragma unroll
        for (int p = 0; p < 2; p++) {
            float r0[4], r1[4];
#pragma unroll
            for (int n = 0; n < 4; n++) unpack2(acc[p][n], r0[n], r1[n]);
            float4 o0 = make_float4(r0[0] + bb.x, r0[1] + bb.y, r0[2] + bb.z, r0[3] + bb.w);
            float4 o1 = make_float4(r1[0] + bb.x, r1[1] + bb.y, r1[2] + bb.z, r1[3] + bb.w);
            *(float4*)(g_xg2 + (size_t)(m0 + ty * 4 + 2 * p)     * 600 + nbase) = o0;
            *(float4*)(g_xg2 + (size_t)(m0 + ty * 4 + 2 * p + 1) * 600 + nbase) = o1;
        }
    }
}

// ---------------------------------------------------------------------------
// lstm2 forward recurrence. 128 CTAs x 8 batches, 384 threads.
// Threads 0..299 own TWO contiguous gate rows (r0 = 2*tid, r0+1).
// k2<42 weight slab in smem (201.6 KB); k2 42..75 streamed via depth-4 ring.
// smem floats: Wlo 42*600*2=50400 | gates 8*608=4864 | h 8*152=1216 -> 225920 B
// ---------------------------------------------------------------------------
#define L2_SMEM_BYTES 225920

extern __shared__ float lstm2_sm[];

__global__ __launch_bounds__(384, 1) void lstm2_kernel()
{
    float2* Wlo  = (float2*)lstm2_sm;                 // [k2*600 + r], k2 < 42
    float* gates = lstm2_sm + 50400;                  // [8][608]
    float* h_s   = lstm2_sm + 50400 + 4864;           // [8][152]

    const int tid = threadIdx.x;
    const int b0  = blockIdx.x * 8;
    const bool comp = (tid < 300);
    const int r0 = tid * 2;                           // rows r0, r0+1

    // load smem-resident weight slab (42*600 float2 = 12600 float4)
    for (int i = tid; i < 12600; i += 384)
        ((float4*)lstm2_sm)[i] = ((const float4*)g_W2p)[i];
    for (int i = tid; i < 8 * 152; i += 384) h_s[i] = 0.f;

    // update-phase slots: s = tid + i*384 (1200 total)
    int bs[4], js[4];
    float cs[4];
#pragma unroll
    for (int i = 0; i < 4; i++) {
        int s = tid + i * 384;
        if (s < 1200) { bs[i] = s / 150; js[i] = s - bs[i] * 150; }
        else          { bs[i] = 0;       js[i] = 0; }
        cs[i] = 0.f;
    }

    const float* xbase = g_xg2 + (size_t)b0 * 76800 + r0;   // + b*76800 + t*600

    // x prefetch registers (t = 0)
    float2 xp[8];
    if (comp) {
#pragma unroll
        for (int b = 0; b < 8; b++)
            xp[b] = *(const float2*)(xbase + (size_t)b * 76800);
    }
    __syncthreads();

    for (int t = 0; t < T_SZ; t++) {
        if (comp) {
            ull a0[8], a1[8];                          // acc for rows r0, r0+1
#pragma unroll
            for (int b = 0; b < 8; b++) {
                a0[b] = pack2(xp[b].x, 0.f);
                a1[b] = pack2(xp[b].y, 0.f);
            }
            // prefetch x for t+1 (hidden under this step's compute)
            if (t < 127) {
#pragma unroll
                for (int b = 0; b < 8; b++)
                    xp[b] = *(const float2*)(xbase + (size_t)b * 76800 + (t + 1) * 600);
            }

            // prefetch ring for streamed weights (iters 21..24)
            ulonglong2 wpa[4], wpb[4];
#pragma unroll
            for (int p = 0; p < 4; p++) {
                wpa[p] = __ldg((const ulonglong2*)(g_W2p + (2 * (21 + p))     * 600 + r0));
                wpb[p] = __ldg((const ulonglong2*)(g_W2p + (2 * (21 + p) + 1) * 600 + r0));
            }

            // ---- smem-resident half: k2 = 0..41 (21 iters x 2 k2) ----
#pragma unroll
            for (int it = 0; it < 21; it++) {
                ulonglong2 wA = *(const ulonglong2*)(Wlo + (2 * it)     * 600 + r0);
                ulonglong2 wB = *(const ulonglong2*)(Wlo + (2 * it + 1) * 600 + r0);
#pragma unroll
                for (int b = 0; b < 8; b++) {
                    ulonglong2 hv = *(const ulonglong2*)(h_s + b * 152 + it * 4);
                    fma2(a0[b], hv.x, wA.x);
                    fma2(a0[b], hv.y, wB.x);
                    fma2(a1[b], hv.x, wA.y);
                    fma2(a1[b], hv.y, wB.y);
                }
            }
            // ---- L2-streamed half: k2 = 42..75, depth-4 rolling prefetch ----
#pragma unroll
            for (int it = 21; it < 38; it++) {
                const int slot = (it - 21) & 3;
                ulonglong2 wA = wpa[slot];
                ulonglong2 wB = wpb[slot];
                if (it + 4 < 38) {
                    wpa[slot] = __ldg((const ulonglong2*)(g_W2p + (2 * (it + 4))     * 600 + r0));
                    wpb[slot] = __ldg((const ulonglong2*)(g_W2p + (2 * (it + 4) + 1) * 600 + r0));
                }
#pragma unroll
                for (int b = 0; b < 8; b++) {
                    ulonglong2 hv = *(const ulonglong2*)(h_s + b * 152 + it * 4);
                    fma2(a0[b], hv.x, wA.x);
                    fma2(a0[b], hv.y, wB.x);
                    fma2(a1[b], hv.x, wA.y);
                    fma2(a1[b], hv.y, wB.y);
                }
            }

#pragma unroll
            for (int b = 0; b < 8; b++) {
                float l0, h0, l1, h1;
                unpack2(a0[b], l0, h0);
                unpack2(a1[b], l1, h1);
                *(float2*)(gates + b * 608 + r0) = make_float2(l0 + h0, l1 + h1);
            }
        }
        __syncthreads();

#pragma unroll
        for (int i = 0; i < 4; i++) {
            int s = tid + i * 384;
            if (s < 1200) {
                int b = bs[i], j = js[i];
                float gi = gates[b * 608 + j];
                float gf = gates[b * 608 + 150 + j];
                float gg = gates[b * 608 + 300 + j];
                float go = gates[b * 608 + 450 + j];
                float c = sigm(gf) * cs[i] + sigm(gi) * tanh_(gg);
                cs[i] = c;
                float h = sigm(go) * tanh_(c);
                h_s[b * 152 + j] = h;
                if (t == 127) g_net[(size_t)(b0 + b) * 300 + j] = h;
            }
        }
        __syncthreads();
    }
}

// ---------------------------------------------------------------------------
// bwd2: layer2 backward needs only its first step (t = T-1, h0 = c0 = 0).
// ---------------------------------------------------------------------------
__global__ __launch_bounds__(256) void bwd2_kernel(
    const float* __restrict__ Wih2b, const float* __restrict__ b2b)
{
    __shared__ float xv[4 * 100];
    __shared__ float gsm[4 * 600];
    const int tid = threadIdx.x;
    const int b0  = blockIdx.x * 4;

    for (int i = tid; i < 400; i += 256) {
        int b = i / 100, c = i - b * 100;
        xv[i] = g_out1[(size_t)(b0 + b) * 12800 + 127 * 100 + c];
    }
    __syncthreads();

    for (int p = tid; p < 2400; p += 256) {
        int b = p / 600, rr = p - b * 600;
        float acc = b2b[rr];
        const float* Wr = Wih2b + rr * 100;
        const float* xr = xv + b * 100;
#pragma unroll 4
        for (int k = 0; k < 100; k++) acc = fmaf(Wr[k], xr[k], acc);
        gsm[b * 600 + rr] = acc;
    }
    __syncthreads();

    for (int p = tid; p < 600; p += 256) {
        int b = p / 150, j = p - b * 150;
        float gi = gsm[b * 600 + j];
        float gg = gsm[b * 600 + 300 + j];
        float go = gsm[b * 600 + 450 + j];
        float c = sigm(gi) * tanh_(gg);           // c0 = 0 -> forget term vanishes
        float h = sigm(go) * tanh_(c);
        g_net[(size_t)(b0 + b) * 300 + 150 + j] = h;
    }
}

// ---------------------------------------------------------------------------
// heads: one 32-thread block per batch.
// ---------------------------------------------------------------------------
__global__ __launch_bounds__(32) void heads_kernel(
    const float* __restrict__ rrs,
    const float* __restrict__ head_W, const float* __restrict__ head_b,
    const float* __restrict__ pef1_W, const float* __restrict__ pef1_b,
    const float* __restrict__ pef2_W, const float* __restrict__ pef2_b,
    const float* __restrict__ fc_W,   const float* __restrict__ fc_b,
    float* __restrict__ out)
{
    __shared__ float net_s[300];
    __shared__ float feat_s[30];
    __shared__ float rrs_s[4];
    const int b = blockIdx.x;
    const int tid = threadIdx.x;

    for (int i = tid; i < 300; i += 32) net_s[i] = g_net[(size_t)b * 300 + i];
    if (tid < 4) rrs_s[tid] = rrs[b * 4 + tid];
    __syncthreads();

    if (tid < 20) {
        float acc = head_b[tid];
        const float* Wr = head_W + tid * 300;
        for (int k = 0; k < 300; k++) acc = fmaf(Wr[k], net_s[k], acc);
        float v = lrelu(acc);
        feat_s[tid] = v;
        out[OFF_WF + b * 20 + tid] = v;
    } else if (tid < 30) {
        int j = tid - 20;
        float acc = pef1_b[j];
#pragma unroll
        for (int k = 0; k < 4; k++) acc = fmaf(pef1_W[j * 4 + k], rrs_s[k], acc);
        feat_s[20 + j] = lrelu(acc);
    }
    __syncthreads();

    if (tid < 2) {
        float acc = pef2_b[tid];
#pragma unroll
        for (int k = 0; k < 10; k++) acc = fmaf(pef2_W[tid * 10 + k], feat_s[20 + k], acc);
        out[OFF_PL + b * 2 + tid] = acc;
    } else if (tid < 6) {
        int j = tid - 2;
        float acc = fc_b[j];
#pragma unroll
        for (int k = 0; k < 30; k++) acc = fmaf(fc_W[j * 30 + k], feat_s[k], acc);
        out[OFF_LG + b * 4 + j] = acc;
    }
    if (tid < 30) out[OFF_FEAT + b * 30 + tid] = feat_s[tid];
}

// ---------------------------------------------------------------------------
extern "C" void kernel_launch(void* const* d_in, const int* in_sizes, int n_in,
                              void* d_out, int out_size)
{
    const float* x        = (const float*)d_in[0];
    const float* rrs      = (const float*)d_in[1];
    const float* l1_Wih_f = (const float*)d_in[2];
    const float* l1_Whh_f = (const float*)d_in[3];
    const float* l1_b_f   = (const float*)d_in[4];
    const float* l1_Wih_b = (const float*)d_in[5];
    const float* l1_Whh_b = (const float*)d_in[6];
    const float* l1_b_b   = (const float*)d_in[7];
    const float* l2_Wih_f = (const float*)d_in[8];
    const float* l2_Whh_f = (const float*)d_in[9];
    const float* l2_b_f   = (const float*)d_in[10];
    const float* l2_Wih_b = (const float*)d_in[11];
    /* d_in[12] = l2_Whh_b unused (single backward step from h0=0) */
    const float* l2_b_b   = (const float*)d_in[13];
    const float* head_W   = (const float*)d_in[14];
    const float* head_b   = (const float*)d_in[15];
    const float* pef1_W   = (const float*)d_in[16];
    const float* pef1_b   = (const float*)d_in[17];
    const float* pef2_W   = (const float*)d_in[18];
    const float* pef2_b   = (const float*)d_in[19];
    const float* fc_W     = (const float*)d_in[20];
    const float* fc_b     = (const float*)d_in[21];
    float* out = (float*)d_out;

    (void)cudaFuncSetAttribute(lstm2_kernel,
                               cudaFuncAttributeMaxDynamicSharedMemorySize, L2_SMEM_BYTES);
    (void)cudaFuncSetAttribute(xg2_kernel,
                               cudaFuncAttributeMaxDynamicSharedMemorySize, XG2_SMEM_BYTES);

    prep_kernel<<<(76 * 600 + 255) / 256, 256>>>(l2_Whh_f);
    lstm1_kernel<<<dim3(128, 2), 256>>>(x, l1_Wih_f, l1_Whh_f, l1_b_f,
                                           l1_Wih_b, l1_Whh_b, l1_b_b);
    xg2_kernel<<<dim3(2048, 10), 256, XG2_SMEM_BYTES>>>(l2_Wih_f, l2_b_f);
    lstm2_kernel<<<128, 384, L2_SMEM_BYTES>>>();
    bwd2_kernel<<<256, 256>>>(l2_Wih_b, l2_b_b);
    heads_kernel<<<1024, 32>>>(rrs, head_W, head_b, pef1_W, pef1_b,
                               pef2_W, pef2_b, fc_W, fc_b, out);
}

// round 10
// speedup vs baseline: 1.0706x; 1.0706x over previous
#include <cuda_runtime.h>
#include <math.h>

// B=1024, T=128, H1=50 (G1=200), H2=150 (G2=600), D2=100
#define B_SZ 1024
#define T_SZ 128

// output: concat of flattened (waveform_feat[1024,20], pef_logits[1024,2],
//                              feat[1024,30], logits[1024,4])
#define OFF_WF   0
#define OFF_PL   20480
#define OFF_FEAT 22528
#define OFF_LG   53248

typedef unsigned long long ull;

static __device__ float  g_out1[(size_t)B_SZ * T_SZ * 100];   // layer1 output (52 MB)
static __device__ float  g_xg2 [(size_t)B_SZ * T_SZ * 600];   // layer2 fwd input proj (315 MB)
static __device__ float2 g_W2p [76 * 600];                    // layer2 fwd Whh, k-pair-major
static __device__ float  g_net [(size_t)B_SZ * 300];          // out2[:, -1]

// ---------------- fast math helpers ----------------
__device__ __forceinline__ float tanh_(float x) {
    float r; asm("tanh.approx.f32 %0, %1;" : "=f"(r) : "f"(x)); return r;
}
__device__ __forceinline__ float sigm(float x) {
    return fmaf(tanh_(0.5f * x), 0.5f, 0.5f);
}
__device__ __forceinline__ float lrelu(float x) { return x > 0.f ? x : 0.3f * x; }

__device__ __forceinline__ ull pack2(float lo, float hi) {
    ull r;
    asm("mov.b64 %0, {%1, %2};" : "=l"(r) : "r"(__float_as_uint(lo)), "r"(__float_as_uint(hi)));
    return r;
}
__device__ __forceinline__ void unpack2(ull v, float& lo, float& hi) {
    unsigned int a, b;
    asm("mov.b64 {%0, %1}, %2;" : "=r"(a), "=r"(b) : "l"(v));
    lo = __uint_as_float(a); hi = __uint_as_float(b);
}
__device__ __forceinline__ void fma2(ull& d, ull a, ull b) {
    asm("fma.rn.f32x2 %0, %1, %2, %3;" : "=l"(d) : "l"(a), "l"(b), "l"(d));
}

// ---------------------------------------------------------------------------
// prep: l2_Whh_f (600x150) -> g_W2p[k2][r] = (W[2k2][r], W[2k2+1][r]), k>=150 -> 0
// ---------------------------------------------------------------------------
__global__ void prep_kernel(const float* __restrict__ Whh2f)
{
    int i = blockIdx.x * 256 + threadIdx.x;
    if (i < 76 * 600) {
        int k2 = i / 600, r = i - k2 * 600;
        float lo = (2 * k2     < 150) ? Whh2f[r * 150 + 2 * k2]     : 0.f;
        float hi = (2 * k2 + 1 < 150) ? Whh2f[r * 150 + 2 * k2 + 1] : 0.f;
        g_W2p[i] = make_float2(lo, hi);
    }
}

// ---------------------------------------------------------------------------
// lstm1: grid (64, 2) = (batch groups of 16, direction), 256 threads.
// (R7 proven configuration)
// ---------------------------------------------------------------------------
__global__ __launch_bounds__(256) void lstm1_kernel(
    const float* __restrict__ x,
    const float* __restrict__ Wih_f, const float* __restrict__ Whh_f, const float* __restrict__ b_f,
    const float* __restrict__ Wih_b, const float* __restrict__ Whh_b, const float* __restrict__ b_b)
{
    __shared__ __align__(16) float h_s[16 * 52];
    __shared__ float c_s[16 * 50];
    __shared__ float gates_s[16 * 200];
    __shared__ float x_s[16 * 128];

    const int tid = threadIdx.x;
    const int dir = blockIdx.y;
    const int b0  = blockIdx.x * 16;

    const float* Wih = dir ? Wih_b : Wih_f;
    const float* Whh = dir ? Whh_b : Whh_f;
    const float* bb  = dir ? b_b   : b_f;

    for (int i = tid; i < 16 * 128; i += 256) {
        int b = i >> 7, t = i & 127;
        x_s[i] = x[(size_t)(b0 + b) * 128 + t];
    }
    for (int i = tid; i < 16 * 52; i += 256) h_s[i] = 0.f;
    for (int i = tid; i < 16 * 50; i += 256) c_s[i] = 0.f;

    ull w2[26];
    float wih = 0.f, bv = 0.f;
    if (tid < 200) {
#pragma unroll
        for (int k2 = 0; k2 < 26; k2++) {
            float lo = (2 * k2     < 50) ? Whh[tid * 50 + 2 * k2]     : 0.f;
            float hi = (2 * k2 + 1 < 50) ? Whh[tid * 50 + 2 * k2 + 1] : 0.f;
            w2[k2] = pack2(lo, hi);
        }
        wih = Wih[tid];
        bv  = bb[tid];
    }
    __syncthreads();

    for (int s = 0; s < T_SZ; s++) {
        const int t = dir ? (127 - s) : s;
        if (tid < 200) {
#pragma unroll 2
            for (int b = 0; b < 16; b++) {
                ull acc = pack2(fmaf(x_s[b * 128 + t], wih, bv), 0.f);
#pragma unroll
                for (int k4 = 0; k4 < 13; k4++) {
                    ulonglong2 hv = *(const ulonglong2*)(h_s + b * 52 + k4 * 4);
                    fma2(acc, hv.x, w2[2 * k4]);
                    fma2(acc, hv.y, w2[2 * k4 + 1]);
                }
                float lo, hi; unpack2(acc, lo, hi);
                gates_s[b * 200 + tid] = lo + hi;
            }
        }
        __syncthreads();
        for (int p = tid; p < 16 * 50; p += 256) {
            int b = p / 50, j = p - b * 50;
            float gi = gates_s[b * 200 + j];
            float gf = gates_s[b * 200 + 50 + j];
            float gg = gates_s[b * 200 + 100 + j];
            float go = gates_s[b * 200 + 150 + j];
            float c = sigm(gf) * c_s[b * 50 + j] + sigm(gi) * tanh_(gg);
            c_s[b * 50 + j] = c;
            float h = sigm(go) * tanh_(c);
            h_s[b * 52 + j] = h;
            g_out1[(size_t)(b0 + b) * 12800 + (size_t)t * 100 + dir * 50 + j] = h;
        }
        __syncthreads();
    }
}

// ---------------------------------------------------------------------------
// xg2 GEMM: C[m][g] = out1[m][:100] . Wih2_f[g][:100] + b2_f[g]
// M = 131072, K = 100, N = 600.  BM=64, BN=64, 256 threads, 4x4 tiles.
// ks-split (two K=50 stages) keeps smem at 40.8 KB -> 5 CTAs/SM, while B is
// stored pre-duplicated ((b,b) ulls) so inner loop = 3 LDS + 8 fma2, no ALU.
// ---------------------------------------------------------------------------
#define XG2_SMEM_BYTES (50 * 68 * 4 + 50 * 68 * 8)   // A_s + B2_s = 40800

extern __shared__ float xg2_sm[];

__global__ __launch_bounds__(256) void xg2_kernel(
    const float* __restrict__ W, const float* __restrict__ bias)
{
    float* A_s  = xg2_sm;                     // [k*68 + m], 50 x 68 floats
    ull*   B2_s = (ull*)(xg2_sm + 50 * 68);   // [k*68 + n], 50 x 68 ulls, (b,b)

    const int m0 = blockIdx.x * 64;
    const int n0 = blockIdx.y * 64;
    const int tid = threadIdx.x;
    const int tx = tid & 15;   // n
    const int ty = tid >> 4;   // m

    ull acc[2][4];   // [m-pair p][n]; lo = row ty*4+2p, hi = row ty*4+2p+1
#pragma unroll
    for (int p = 0; p < 2; p++)
#pragma unroll
        for (int n = 0; n < 4; n++) acc[p][n] = pack2(0.f, 0.f);

    for (int ks = 0; ks < 2; ks++) {
        for (int i = tid; i < 3200; i += 256) {
            int mm = i / 50, kk = i - mm * 50;
            A_s[kk * 68 + mm] = g_out1[(size_t)(m0 + mm) * 100 + ks * 50 + kk];
        }
        for (int i = tid; i < 3200; i += 256) {
            int nn = i / 50, kk = i - nn * 50;
            int g = n0 + nn;
            float v = (g < 600) ? W[g * 100 + ks * 50 + kk] : 0.f;
            B2_s[kk * 68 + nn] = pack2(v, v);
        }
        __syncthreads();
#pragma unroll 10
        for (int k = 0; k < 50; k++) {
            ulonglong2 am  = *(const ulonglong2*)(A_s + k * 68 + ty * 4);      // (m0,m1),(m2,m3)
            ulonglong2 b01 = *(const ulonglong2*)(B2_s + k * 68 + tx * 4);     // splat n0, n1
            ulonglong2 b23 = *(const ulonglong2*)(B2_s + k * 68 + tx * 4 + 2); // splat n2, n3
            fma2(acc[0][0], am.x, b01.x); fma2(acc[0][1], am.x, b01.y);
            fma2(acc[0][2], am.x, b23.x); fma2(acc[0][3], am.x, b23.y);
            fma2(acc[1][0], am.y, b01.x); fma2(acc[1][1], am.y, b01.y);
            fma2(acc[1][2], am.y, b23.x); fma2(acc[1][3], am.y, b23.y);
        }
        __syncthreads();
    }

    const int nbase = n0 + tx * 4;
    if (nbase < 600) {
        float4 bb = *(const float4*)(bias + nbase);
#pragma unroll
        for (int p = 0; p < 2; p++) {
            float r0[4], r1[4];
#pragma unroll
            for (int n = 0; n < 4; n++) unpack2(acc[p][n], r0[n], r1[n]);
            float4 o0 = make_float4(r0[0] + bb.x, r0[1] + bb.y, r0[2] + bb.z, r0[3] + bb.w);
            float4 o1 = make_float4(r1[0] + bb.x, r1[1] + bb.y, r1[2] + bb.z, r1[3] + bb.w);
            *(float4*)(g_xg2 + (size_t)(m0 + ty * 4 + 2 * p)     * 600 + nbase) = o0;
            *(float4*)(g_xg2 + (size_t)(m0 + ty * 4 + 2 * p + 1) * 600 + nbase) = o1;
        }
    }
}

// ---------------------------------------------------------------------------
// lstm2 forward recurrence (R7 proven: 38-k2 slab). 128 CTAs x 8 batches,
// 384 threads; threads 0..299 own rows r0=2*tid, r0+1. Streamed k2 38..75
// via depth-4 register prefetch ring; x[t+1] register-prefetched.
// smem floats: Wlo 38*600*2=45600 | gates 8*608=4864 | h 8*152=1216 -> 206720 B
// ---------------------------------------------------------------------------
#define L2_SMEM_BYTES 206720

extern __shared__ float lstm2_sm[];

__global__ __launch_bounds__(384, 1) void lstm2_kernel()
{
    float2* Wlo  = (float2*)lstm2_sm;                 // [k2*600 + r], k2 < 38
    float* gates = lstm2_sm + 45600;                  // [8][608]
    float* h_s   = lstm2_sm + 45600 + 4864;           // [8][152]

    const int tid = threadIdx.x;
    const int b0  = blockIdx.x * 8;
    const bool comp = (tid < 300);
    const int r0 = tid * 2;                           // rows r0, r0+1

    for (int i = tid; i < 11400; i += 384)
        ((float4*)lstm2_sm)[i] = ((const float4*)g_W2p)[i];
    for (int i = tid; i < 8 * 152; i += 384) h_s[i] = 0.f;

    int bs[4], js[4];
    float cs[4];
#pragma unroll
    for (int i = 0; i < 4; i++) {
        int s = tid + i * 384;
        if (s < 1200) { bs[i] = s / 150; js[i] = s - bs[i] * 150; }
        else          { bs[i] = 0;       js[i] = 0; }
        cs[i] = 0.f;
    }

    const float* xbase = g_xg2 + (size_t)b0 * 76800 + r0;   // + b*76800 + t*600

    float2 xp[8];
    if (comp) {
#pragma unroll
        for (int b = 0; b < 8; b++)
            xp[b] = *(const float2*)(xbase + (size_t)b * 76800);
    }
    __syncthreads();

    for (int t = 0; t < T_SZ; t++) {
        if (comp) {
            ull a0[8], a1[8];
#pragma unroll
            for (int b = 0; b < 8; b++) {
                a0[b] = pack2(xp[b].x, 0.f);
                a1[b] = pack2(xp[b].y, 0.f);
            }
            if (t < 127) {
#pragma unroll
                for (int b = 0; b < 8; b++)
                    xp[b] = *(const float2*)(xbase + (size_t)b * 76800 + (t + 1) * 600);
            }

            ulonglong2 wpa[4], wpb[4];
#pragma unroll
            for (int p = 0; p < 4; p++) {
                wpa[p] = __ldg((const ulonglong2*)(g_W2p + (2 * (19 + p))     * 600 + r0));
                wpb[p] = __ldg((const ulonglong2*)(g_W2p + (2 * (19 + p) + 1) * 600 + r0));
            }

#pragma unroll
            for (int it = 0; it < 19; it++) {
                ulonglong2 wA = *(const ulonglong2*)(Wlo + (2 * it)     * 600 + r0);
                ulonglong2 wB = *(const ulonglong2*)(Wlo + (2 * it + 1) * 600 + r0);
#pragma unroll
                for (int b = 0; b < 8; b++) {
                    ulonglong2 hv = *(const ulonglong2*)(h_s + b * 152 + it * 4);
                    fma2(a0[b], hv.x, wA.x);
                    fma2(a0[b], hv.y, wB.x);
                    fma2(a1[b], hv.x, wA.y);
                    fma2(a1[b], hv.y, wB.y);
                }
            }
#pragma unroll
            for (int it = 19; it < 38; it++) {
                const int slot = (it - 19) & 3;
                ulonglong2 wA = wpa[slot];
                ulonglong2 wB = wpb[slot];
                if (it + 4 < 38) {
                    wpa[slot] = __ldg((const ulonglong2*)(g_W2p + (2 * (it + 4))     * 600 + r0));
                    wpb[slot] = __ldg((const ulonglong2*)(g_W2p + (2 * (it + 4) + 1) * 600 + r0));
                }
#pragma unroll
                for (int b = 0; b < 8; b++) {
                    ulonglong2 hv = *(const ulonglong2*)(h_s + b * 152 + it * 4);
                    fma2(a0[b], hv.x, wA.x);
                    fma2(a0[b], hv.y, wB.x);
                    fma2(a1[b], hv.x, wA.y);
                    fma2(a1[b], hv.y, wB.y);
                }
            }

#pragma unroll
            for (int b = 0; b < 8; b++) {
                float l0, h0, l1, h1;
                unpack2(a0[b], l0, h0);
                unpack2(a1[b], l1, h1);
                *(float2*)(gates + b * 608 + r0) = make_float2(l0 + h0, l1 + h1);
            }
        }
        __syncthreads();

#pragma unroll
        for (int i = 0; i < 4; i++) {
            int s = tid + i * 384;
            if (s < 1200) {
                int b = bs[i], j = js[i];
                float gi = gates[b * 608 + j];
                float gf = gates[b * 608 + 150 + j];
                float gg = gates[b * 608 + 300 + j];
                float go = gates[b * 608 + 450 + j];
                float c = sigm(gf) * cs[i] + sigm(gi) * tanh_(gg);
                cs[i] = c;
                float h = sigm(go) * tanh_(c);
                h_s[b * 152 + j] = h;
                if (t == 127) g_net[(size_t)(b0 + b) * 300 + j] = h;
            }
        }
        __syncthreads();
    }
}

// ---------------------------------------------------------------------------
// bwd2: layer2 backward needs only its first step (t = T-1, h0 = c0 = 0).
// ---------------------------------------------------------------------------
__global__ __launch_bounds__(256) void bwd2_kernel(
    const float* __restrict__ Wih2b, const float* __restrict__ b2b)
{
    __shared__ float xv[4 * 100];
    __shared__ float gsm[4 * 600];
    const int tid = threadIdx.x;
    const int b0  = blockIdx.x * 4;

    for (int i = tid; i < 400; i += 256) {
        int b = i / 100, c = i - b * 100;
        xv[i] = g_out1[(size_t)(b0 + b) * 12800 + 127 * 100 + c];
    }
    __syncthreads();

    for (int p = tid; p < 2400; p += 256) {
        int b = p / 600, rr = p - b * 600;
        float acc = b2b[rr];
        const float* Wr = Wih2b + rr * 100;
        const float* xr = xv + b * 100;
#pragma unroll 4
        for (int k = 0; k < 100; k++) acc = fmaf(Wr[k], xr[k], acc);
        gsm[b * 600 + rr] = acc;
    }
    __syncthreads();

    for (int p = tid; p < 600; p += 256) {
        int b = p / 150, j = p - b * 150;
        float gi = gsm[b * 600 + j];
        float gg = gsm[b * 600 + 300 + j];
        float go = gsm[b * 600 + 450 + j];
        float c = sigm(gi) * tanh_(gg);           // c0 = 0 -> forget term vanishes
        float h = sigm(go) * tanh_(c);
        g_net[(size_t)(b0 + b) * 300 + 150 + j] = h;
    }
}

// ---------------------------------------------------------------------------
// heads: one 32-thread block per batch.
// ---------------------------------------------------------------------------
__global__ __launch_bounds__(32) void heads_kernel(
    const float* __restrict__ rrs,
    const float* __restrict__ head_W, const float* __restrict__ head_b,
    const float* __restrict__ pef1_W, const float* __restrict__ pef1_b,
    const float* __restrict__ pef2_W, const float* __restrict__ pef2_b,
    const float* __restrict__ fc_W,   const float* __restrict__ fc_b,
    float* __restrict__ out)
{
    __shared__ float net_s[300];
    __shared__ float feat_s[30];
    __shared__ float rrs_s[4];
    const int b = blockIdx.x;
    const int tid = threadIdx.x;

    for (int i = tid; i < 300; i += 32) net_s[i] = g_net[(size_t)b * 300 + i];
    if (tid < 4) rrs_s[tid] = rrs[b * 4 + tid];
    __syncthreads();

    if (tid < 20) {
        float acc = head_b[tid];
        const float* Wr = head_W + tid * 300;
        for (int k = 0; k < 300; k++) acc = fmaf(Wr[k], net_s[k], acc);
        float v = lrelu(acc);
        feat_s[tid] = v;
        out[OFF_WF + b * 20 + tid] = v;
    } else if (tid < 30) {
        int j = tid - 20;
        float acc = pef1_b[j];
#pragma unroll
        for (int k = 0; k < 4; k++) acc = fmaf(pef1_W[j * 4 + k], rrs_s[k], acc);
        feat_s[20 + j] = lrelu(acc);
    }
    __syncthreads();

    if (tid < 2) {
        float acc = pef2_b[tid];
#pragma unroll
        for (int k = 0; k < 10; k++) acc = fmaf(pef2_W[tid * 10 + k], feat_s[20 + k], acc);
        out[OFF_PL + b * 2 + tid] = acc;
    } else if (tid < 6) {
        int j = tid - 2;
        float acc = fc_b[j];
#pragma unroll
        for (int k = 0; k < 30; k++) acc = fmaf(fc_W[j * 30 + k], feat_s[k], acc);
        out[OFF_LG + b * 4 + j] = acc;
    }
    if (tid < 30) out[OFF_FEAT + b * 30 + tid] = feat_s[tid];
}

// ---------------------------------------------------------------------------
extern "C" void kernel_launch(void* const* d_in, const int* in_sizes, int n_in,
                              void* d_out, int out_size)
{
    const float* x        = (const float*)d_in[0];
    const float* rrs      = (const float*)d_in[1];
    const float* l1_Wih_f = (const float*)d_in[2];
    const float* l1_Whh_f = (const float*)d_in[3];
    const float* l1_b_f   = (const float*)d_in[4];
    const float* l1_Wih_b = (const float*)d_in[5];
    const float* l1_Whh_b = (const float*)d_in[6];
    const float* l1_b_b   = (const float*)d_in[7];
    const float* l2_Wih_f = (const float*)d_in[8];
    const float* l2_Whh_f = (const float*)d_in[9];
    const float* l2_b_f   = (const float*)d_in[10];
    const float* l2_Wih_b = (const float*)d_in[11];
    /* d_in[12] = l2_Whh_b unused (single backward step from h0=0) */
    const float* l2_b_b   = (const float*)d_in[13];
    const float* head_W   = (const float*)d_in[14];
    const float* head_b   = (const float*)d_in[15];
    const float* pef1_W   = (const float*)d_in[16];
    const float* pef1_b   = (const float*)d_in[17];
    const float* pef2_W   = (const float*)d_in[18];
    const float* pef2_b   = (const float*)d_in[19];
    const float* fc_W     = (const float*)d_in[20];
    const float* fc_b     = (const float*)d_in[21];
    float* out = (float*)d_out;

    (void)cudaFuncSetAttribute(lstm2_kernel,
                               cudaFuncAttributeMaxDynamicSharedMemorySize, L2_SMEM_BYTES);
    (void)cudaFuncSetAttribute(xg2_kernel,
                               cudaFuncAttributeMaxDynamicSharedMemorySize, XG2_SMEM_BYTES);

    prep_kernel<<<(76 * 600 + 255) / 256, 256>>>(l2_Whh_f);
    lstm1_kernel<<<dim3(64, 2), 256>>>(x, l1_Wih_f, l1_Whh_f, l1_b_f,
                                          l1_Wih_b, l1_Whh_b, l1_b_b);
    xg2_kernel<<<dim3(2048, 10), 256, XG2_SMEM_BYTES>>>(l2_Wih_f, l2_b_f);
    lstm2_kernel<<<128, 384, L2_SMEM_BYTES>>>();
    bwd2_kernel<<<256, 256>>>(l2_Wih_b, l2_b_b);
    heads_kernel<<<1024, 32>>>(rrs, head_W, head_b, pef1_W, pef1_b,
                               pef2_W, pef2_b, fc_W, fc_b, out);
}

// round 11
// speedup vs baseline: 1.3684x; 1.2782x over previous
#include <cuda_runtime.h>
#include <math.h>

// B=1024, T=128, H1=50 (G1=200), H2=150 (G2=600), D2=100
#define B_SZ 1024
#define T_SZ 128

// output: concat of flattened (waveform_feat[1024,20], pef_logits[1024,2],
//                              feat[1024,30], logits[1024,4])
#define OFF_WF   0
#define OFF_PL   20480
#define OFF_FEAT 22528
#define OFF_LG   53248

typedef unsigned long long ull;

static __device__ float  g_out1[(size_t)B_SZ * T_SZ * 100];   // layer1 output (52 MB)
static __device__ float  g_xg2 [(size_t)B_SZ * T_SZ * 600];   // layer2 fwd input proj (315 MB)
static __device__ float2 g_W2p [76 * 600];                    // layer2 fwd Whh, k-pair-major
static __device__ float  g_net [(size_t)B_SZ * 300];          // out2[:, -1]

// ---------------- fast math helpers ----------------
__device__ __forceinline__ float tanh_(float x) {
    float r; asm("tanh.approx.f32 %0, %1;" : "=f"(r) : "f"(x)); return r;
}
__device__ __forceinline__ float sigm(float x) {
    return fmaf(tanh_(0.5f * x), 0.5f, 0.5f);
}
__device__ __forceinline__ float lrelu(float x) { return x > 0.f ? x : 0.3f * x; }

__device__ __forceinline__ ull pack2(float lo, float hi) {
    ull r;
    asm("mov.b64 %0, {%1, %2};" : "=l"(r) : "r"(__float_as_uint(lo)), "r"(__float_as_uint(hi)));
    return r;
}
__device__ __forceinline__ void unpack2(ull v, float& lo, float& hi) {
    unsigned int a, b;
    asm("mov.b64 {%0, %1}, %2;" : "=r"(a), "=r"(b) : "l"(v));
    lo = __uint_as_float(a); hi = __uint_as_float(b);
}
__device__ __forceinline__ void fma2(ull& d, ull a, ull b) {
    asm("fma.rn.f32x2 %0, %1, %2, %3;" : "=l"(d) : "l"(a), "l"(b), "l"(d));
}

// ---------------------------------------------------------------------------
// prep: l2_Whh_f (600x150) -> g_W2p[k2][r] = (W[2k2][r], W[2k2+1][r]), k>=150 -> 0
// ---------------------------------------------------------------------------
__global__ void prep_kernel(const float* __restrict__ Whh2f)
{
    int i = blockIdx.x * 256 + threadIdx.x;
    if (i < 76 * 600) {
        int k2 = i / 600, r = i - k2 * 600;
        float lo = (2 * k2     < 150) ? Whh2f[r * 150 + 2 * k2]     : 0.f;
        float hi = (2 * k2 + 1 < 150) ? Whh2f[r * 150 + 2 * k2 + 1] : 0.f;
        g_W2p[i] = make_float2(lo, hi);
    }
}

// ---------------------------------------------------------------------------
// lstm1: grid (64, 2) = (batch groups of 16, direction), 256 threads.
// (R7 proven configuration)
// ---------------------------------------------------------------------------
__global__ __launch_bounds__(256) void lstm1_kernel(
    const float* __restrict__ x,
    const float* __restrict__ Wih_f, const float* __restrict__ Whh_f, const float* __restrict__ b_f,
    const float* __restrict__ Wih_b, const float* __restrict__ Whh_b, const float* __restrict__ b_b)
{
    __shared__ __align__(16) float h_s[16 * 52];
    __shared__ float c_s[16 * 50];
    __shared__ float gates_s[16 * 200];
    __shared__ float x_s[16 * 128];

    const int tid = threadIdx.x;
    const int dir = blockIdx.y;
    const int b0  = blockIdx.x * 16;

    const float* Wih = dir ? Wih_b : Wih_f;
    const float* Whh = dir ? Whh_b : Whh_f;
    const float* bb  = dir ? b_b   : b_f;

    for (int i = tid; i < 16 * 128; i += 256) {
        int b = i >> 7, t = i & 127;
        x_s[i] = x[(size_t)(b0 + b) * 128 + t];
    }
    for (int i = tid; i < 16 * 52; i += 256) h_s[i] = 0.f;
    for (int i = tid; i < 16 * 50; i += 256) c_s[i] = 0.f;

    ull w2[26];
    float wih = 0.f, bv = 0.f;
    if (tid < 200) {
#pragma unroll
        for (int k2 = 0; k2 < 26; k2++) {
            float lo = (2 * k2     < 50) ? Whh[tid * 50 + 2 * k2]     : 0.f;
            float hi = (2 * k2 + 1 < 50) ? Whh[tid * 50 + 2 * k2 + 1] : 0.f;
            w2[k2] = pack2(lo, hi);
        }
        wih = Wih[tid];
        bv  = bb[tid];
    }
    __syncthreads();

    for (int s = 0; s < T_SZ; s++) {
        const int t = dir ? (127 - s) : s;
        if (tid < 200) {
#pragma unroll 2
            for (int b = 0; b < 16; b++) {
                ull acc = pack2(fmaf(x_s[b * 128 + t], wih, bv), 0.f);
#pragma unroll
                for (int k4 = 0; k4 < 13; k4++) {
                    ulonglong2 hv = *(const ulonglong2*)(h_s + b * 52 + k4 * 4);
                    fma2(acc, hv.x, w2[2 * k4]);
                    fma2(acc, hv.y, w2[2 * k4 + 1]);
                }
                float lo, hi; unpack2(acc, lo, hi);
                gates_s[b * 200 + tid] = lo + hi;
            }
        }
        __syncthreads();
        for (int p = tid; p < 16 * 50; p += 256) {
            int b = p / 50, j = p - b * 50;
            float gi = gates_s[b * 200 + j];
            float gf = gates_s[b * 200 + 50 + j];
            float gg = gates_s[b * 200 + 100 + j];
            float go = gates_s[b * 200 + 150 + j];
            float c = sigm(gf) * c_s[b * 50 + j] + sigm(gi) * tanh_(gg);
            c_s[b * 50 + j] = c;
            float h = sigm(go) * tanh_(c);
            h_s[b * 52 + j] = h;
            g_out1[(size_t)(b0 + b) * 12800 + (size_t)t * 100 + dir * 50 + j] = h;
        }
        __syncthreads();
    }
}

// ---------------------------------------------------------------------------
// xg2 GEMM: C[m][g] = out1[m][:100] . Wih2_f[g][:100] + b2_f[g]
// M = 131072, K = 100, N = 600.  BM=64, BN=64, 256 threads, 4x4 tiles.
// A stored DUPLICATED ((a,a) ulls): warp's A loads hit only 2 addresses
// (ty in {0,1} per warp) -> pure broadcast, conflict-free. B stays plain
// floats, loaded as contiguous 16B pairs (R7 pattern, conflict-free).
// Inner loop per k: 3 LDS.128 + 8 fma2, ZERO splat MOVs.
// smem: A2_s 50*68 ulls (27.2 KB) + B_s 50*68 floats (13.6 KB) = 40.8 KB
// ---------------------------------------------------------------------------
#define XG2_SMEM_BYTES (50 * 68 * 8 + 50 * 68 * 4)

extern __shared__ float xg2_sm[];

__global__ __launch_bounds__(256) void xg2_kernel(
    const float* __restrict__ W, const float* __restrict__ bias)
{
    ull*   A2_s = (ull*)xg2_sm;                   // [k*68 + m], (a,a) pairs
    float* B_s  = xg2_sm + 2 * 50 * 68;           // [k*68 + n], plain floats

    const int m0 = blockIdx.x * 64;
    const int n0 = blockIdx.y * 64;
    const int tid = threadIdx.x;
    const int tx = tid & 15;   // n
    const int ty = tid >> 4;   // m

    ull acc[4][2];   // [mi][np]: np=0 -> cols (n0+tx*4, +1), np=1 -> (+2, +3)
#pragma unroll
    for (int mi = 0; mi < 4; mi++)
#pragma unroll
        for (int np = 0; np < 2; np++) acc[mi][np] = pack2(0.f, 0.f);

    for (int ks = 0; ks < 2; ks++) {
        for (int i = tid; i < 3200; i += 256) {
            int mm = i / 50, kk = i - mm * 50;
            float v = g_out1[(size_t)(m0 + mm) * 100 + ks * 50 + kk];
            A2_s[kk * 68 + mm] = pack2(v, v);
        }
        for (int i = tid; i < 3200; i += 256) {
            int nn = i / 50, kk = i - nn * 50;
            int g = n0 + nn;
            B_s[kk * 68 + nn] = (g < 600) ? W[g * 100 + ks * 50 + kk] : 0.f;
        }
        __syncthreads();
#pragma unroll 10
        for (int k = 0; k < 50; k++) {
            ulonglong2 am01 = *(const ulonglong2*)(A2_s + k * 68 + ty * 4);     // splat m0, m1
            ulonglong2 am23 = *(const ulonglong2*)(A2_s + k * 68 + ty * 4 + 2); // splat m2, m3
            ulonglong2 bv   = *(const ulonglong2*)(B_s  + k * 68 + tx * 4);     // (n0,n1),(n2,n3)
            fma2(acc[0][0], am01.x, bv.x); fma2(acc[0][1], am01.x, bv.y);
            fma2(acc[1][0], am01.y, bv.x); fma2(acc[1][1], am01.y, bv.y);
            fma2(acc[2][0], am23.x, bv.x); fma2(acc[2][1], am23.x, bv.y);
            fma2(acc[3][0], am23.y, bv.x); fma2(acc[3][1], am23.y, bv.y);
        }
        __syncthreads();
    }

    const int nbase = n0 + tx * 4;
    if (nbase < 600) {
        float4 bb = *(const float4*)(bias + nbase);
#pragma unroll
        for (int mi = 0; mi < 4; mi++) {
            float4 o;
            unpack2(acc[mi][0], o.x, o.y);
            unpack2(acc[mi][1], o.z, o.w);
            o.x += bb.x; o.y += bb.y; o.z += bb.z; o.w += bb.w;
            *(float4*)(g_xg2 + (size_t)(m0 + ty * 4 + mi) * 600 + nbase) = o;
        }
    }
}

// ---------------------------------------------------------------------------
// lstm2 forward recurrence (R7 proven: 38-k2 slab). 128 CTAs x 8 batches,
// 384 threads; threads 0..299 own rows r0=2*tid, r0+1. Streamed k2 38..75
// via depth-4 register prefetch ring; x[t+1] register-prefetched.
// smem floats: Wlo 38*600*2=45600 | gates 8*608=4864 | h 8*152=1216 -> 206720 B
// ---------------------------------------------------------------------------
#define L2_SMEM_BYTES 206720

extern __shared__ float lstm2_sm[];

__global__ __launch_bounds__(384, 1) void lstm2_kernel()
{
    float2* Wlo  = (float2*)lstm2_sm;                 // [k2*600 + r], k2 < 38
    float* gates = lstm2_sm + 45600;                  // [8][608]
    float* h_s   = lstm2_sm + 45600 + 4864;           // [8][152]

    const int tid = threadIdx.x;
    const int b0  = blockIdx.x * 8;
    const bool comp = (tid < 300);
    const int r0 = tid * 2;                           // rows r0, r0+1

    for (int i = tid; i < 11400; i += 384)
        ((float4*)lstm2_sm)[i] = ((const float4*)g_W2p)[i];
    for (int i = tid; i < 8 * 152; i += 384) h_s[i] = 0.f;

    int bs[4], js[4];
    float cs[4];
#pragma unroll
    for (int i = 0; i < 4; i++) {
        int s = tid + i * 384;
        if (s < 1200) { bs[i] = s / 150; js[i] = s - bs[i] * 150; }
        else          { bs[i] = 0;       js[i] = 0; }
        cs[i] = 0.f;
    }

    const float* xbase = g_xg2 + (size_t)b0 * 76800 + r0;   // + b*76800 + t*600

    float2 xp[8];
    if (comp) {
#pragma unroll
        for (int b = 0; b < 8; b++)
            xp[b] = *(const float2*)(xbase + (size_t)b * 76800);
    }
    __syncthreads();

    for (int t = 0; t < T_SZ; t++) {
        if (comp) {
            ull a0[8], a1[8];
#pragma unroll
            for (int b = 0; b < 8; b++) {
                a0[b] = pack2(xp[b].x, 0.f);
                a1[b] = pack2(xp[b].y, 0.f);
            }
            if (t < 127) {
#pragma unroll
                for (int b = 0; b < 8; b++)
                    xp[b] = *(const float2*)(xbase + (size_t)b * 76800 + (t + 1) * 600);
            }

            ulonglong2 wpa[4], wpb[4];
#pragma unroll
            for (int p = 0; p < 4; p++) {
                wpa[p] = __ldg((const ulonglong2*)(g_W2p + (2 * (19 + p))     * 600 + r0));
                wpb[p] = __ldg((const ulonglong2*)(g_W2p + (2 * (19 + p) + 1) * 600 + r0));
            }

#pragma unroll
            for (int it = 0; it < 19; it++) {
                ulonglong2 wA = *(const ulonglong2*)(Wlo + (2 * it)     * 600 + r0);
                ulonglong2 wB = *(const ulonglong2*)(Wlo + (2 * it + 1) * 600 + r0);
#pragma unroll
                for (int b = 0; b < 8; b++) {
                    ulonglong2 hv = *(const ulonglong2*)(h_s + b * 152 + it * 4);
                    fma2(a0[b], hv.x, wA.x);
                    fma2(a0[b], hv.y, wB.x);
                    fma2(a1[b], hv.x, wA.y);
                    fma2(a1[b], hv.y, wB.y);
                }
            }
#pragma unroll
            for (int it = 19; it < 38; it++) {
                const int slot = (it - 19) & 3;
                ulonglong2 wA = wpa[slot];
                ulonglong2 wB = wpb[slot];
                if (it + 4 < 38) {
                    wpa[slot] = __ldg((const ulonglong2*)(g_W2p + (2 * (it + 4))     * 600 + r0));
                    wpb[slot] = __ldg((const ulonglong2*)(g_W2p + (2 * (it + 4) + 1) * 600 + r0));
                }
#pragma unroll
                for (int b = 0; b < 8; b++) {
                    ulonglong2 hv = *(const ulonglong2*)(h_s + b * 152 + it * 4);
                    fma2(a0[b], hv.x, wA.x);
                    fma2(a0[b], hv.y, wB.x);
                    fma2(a1[b], hv.x, wA.y);
                    fma2(a1[b], hv.y, wB.y);
                }
            }

#pragma unroll
            for (int b = 0; b < 8; b++) {
                float l0, h0, l1, h1;
                unpack2(a0[b], l0, h0);
                unpack2(a1[b], l1, h1);
                *(float2*)(gates + b * 608 + r0) = make_float2(l0 + h0, l1 + h1);
            }
        }
        __syncthreads();

#pragma unroll
        for (int i = 0; i < 4; i++) {
            int s = tid + i * 384;
            if (s < 1200) {
                int b = bs[i], j = js[i];
                float gi = gates[b * 608 + j];
                float gf = gates[b * 608 + 150 + j];
                float gg = gates[b * 608 + 300 + j];
                float go = gates[b * 608 + 450 + j];
                float c = sigm(gf) * cs[i] + sigm(gi) * tanh_(gg);
                cs[i] = c;
                float h = sigm(go) * tanh_(c);
                h_s[b * 152 + j] = h;
                if (t == 127) g_net[(size_t)(b0 + b) * 300 + j] = h;
            }
        }
        __syncthreads();
    }
}

// ---------------------------------------------------------------------------
// bwd2: layer2 backward needs only its first step (t = T-1, h0 = c0 = 0).
// ---------------------------------------------------------------------------
__global__ __launch_bounds__(256) void bwd2_kernel(
    const float* __restrict__ Wih2b, const float* __restrict__ b2b)
{
    __shared__ float xv[4 * 100];
    __shared__ float gsm[4 * 600];
    const int tid = threadIdx.x;
    const int b0  = blockIdx.x * 4;

    for (int i = tid; i < 400; i += 256) {
        int b = i / 100, c = i - b * 100;
        xv[i] = g_out1[(size_t)(b0 + b) * 12800 + 127 * 100 + c];
    }
    __syncthreads();

    for (int p = tid; p < 2400; p += 256) {
        int b = p / 600, rr = p - b * 600;
        float acc = b2b[rr];
        const float* Wr = Wih2b + rr * 100;
        const float* xr = xv + b * 100;
#pragma unroll 4
        for (int k = 0; k < 100; k++) acc = fmaf(Wr[k], xr[k], acc);
        gsm[b * 600 + rr] = acc;
    }
    __syncthreads();

    for (int p = tid; p < 600; p += 256) {
        int b = p / 150, j = p - b * 150;
        float gi = gsm[b * 600 + j];
        float gg = gsm[b * 600 + 300 + j];
        float go = gsm[b * 600 + 450 + j];
        float c = sigm(gi) * tanh_(gg);           // c0 = 0 -> forget term vanishes
        float h = sigm(go) * tanh_(c);
        g_net[(size_t)(b0 + b) * 300 + 150 + j] = h;
    }
}

// ---------------------------------------------------------------------------
// heads: one 32-thread block per batch.
// ---------------------------------------------------------------------------
__global__ __launch_bounds__(32) void heads_kernel(
    const float* __restrict__ rrs,
    const float* __restrict__ head_W, const float* __restrict__ head_b,
    const float* __restrict__ pef1_W, const float* __restrict__ pef1_b,
    const float* __restrict__ pef2_W, const float* __restrict__ pef2_b,
    const float* __restrict__ fc_W,   const float* __restrict__ fc_b,
    float* __restrict__ out)
{
    __shared__ float net_s[300];
    __shared__ float feat_s[30];
    __shared__ float rrs_s[4];
    const int b = blockIdx.x;
    const int tid = threadIdx.x;

    for (int i = tid; i < 300; i += 32) net_s[i] = g_net[(size_t)b * 300 + i];
    if (tid < 4) rrs_s[tid] = rrs[b * 4 + tid];
    __syncthreads();

    if (tid < 20) {
        float acc = head_b[tid];
        const float* Wr = head_W + tid * 300;
        for (int k = 0; k < 300; k++) acc = fmaf(Wr[k], net_s[k], acc);
        float v = lrelu(acc);
        feat_s[tid] = v;
        out[OFF_WF + b * 20 + tid] = v;
    } else if (tid < 30) {
        int j = tid - 20;
        float acc = pef1_b[j];
#pragma unroll
        for (int k = 0; k < 4; k++) acc = fmaf(pef1_W[j * 4 + k], rrs_s[k], acc);
        feat_s[20 + j] = lrelu(acc);
    }
    __syncthreads();

    if (tid < 2) {
        float acc = pef2_b[tid];
#pragma unroll
        for (int k = 0; k < 10; k++) acc = fmaf(pef2_W[tid * 10 + k], feat_s[20 + k], acc);
        out[OFF_PL + b * 2 + tid] = acc;
    } else if (tid < 6) {
        int j = tid - 2;
        float acc = fc_b[j];
#pragma unroll
        for (int k = 0; k < 30; k++) acc = fmaf(fc_W[j * 30 + k], feat_s[k], acc);
        out[OFF_LG + b * 4 + j] = acc;
    }
    if (tid < 30) out[OFF_FEAT + b * 30 + tid] = feat_s[tid];
}

// ---------------------------------------------------------------------------
extern "C" void kernel_launch(void* const* d_in, const int* in_sizes, int n_in,
                              void* d_out, int out_size)
{
    const float* x        = (const float*)d_in[0];
    const float* rrs      = (const float*)d_in[1];
    const float* l1_Wih_f = (const float*)d_in[2];
    const float* l1_Whh_f = (const float*)d_in[3];
    const float* l1_b_f   = (const float*)d_in[4];
    const float* l1_Wih_b = (const float*)d_in[5];
    const float* l1_Whh_b = (const float*)d_in[6];
    const float* l1_b_b   = (const float*)d_in[7];
    const float* l2_Wih_f = (const float*)d_in[8];
    const float* l2_Whh_f = (const float*)d_in[9];
    const float* l2_b_f   = (const float*)d_in[10];
    const float* l2_Wih_b = (const float*)d_in[11];
    /* d_in[12] = l2_Whh_b unused (single backward step from h0=0) */
    const float* l2_b_b   = (const float*)d_in[13];
    const float* head_W   = (const float*)d_in[14];
    const float* head_b   = (const float*)d_in[15];
    const float* pef1_W   = (const float*)d_in[16];
    const float* pef1_b   = (const float*)d_in[17];
    const float* pef2_W   = (const float*)d_in[18];
    const float* pef2_b   = (const float*)d_in[19];
    const float* fc_W     = (const float*)d_in[20];
    const float* fc_b     = (const float*)d_in[21];
    float* out = (float*)d_out;

    (void)cudaFuncSetAttribute(lstm2_kernel,
                               cudaFuncAttributeMaxDynamicSharedMemorySize, L2_SMEM_BYTES);
    (void)cudaFuncSetAttribute(xg2_kernel,
                               cudaFuncAttributeMaxDynamicSharedMemorySize, XG2_SMEM_BYTES);

    prep_kernel<<<(76 * 600 + 255) / 256, 256>>>(l2_Whh_f);
    lstm1_kernel<<<dim3(64, 2), 256>>>(x, l1_Wih_f, l1_Whh_f, l1_b_f,
                                          l1_Wih_b, l1_Whh_b, l1_b_b);
    xg2_kernel<<<dim3(2048, 10), 256, XG2_SMEM_BYTES>>>(l2_Wih_f, l2_b_f);
    lstm2_kernel<<<128, 384, L2_SMEM_BYTES>>>();
    bwd2_kernel<<<256, 256>>>(l2_Wih_b, l2_b_b);
    heads_kernel<<<1024, 32>>>(rrs, head_W, head_b, pef1_W, pef1_b,
                               pef2_W, pef2_b, fc_W, fc_b, out);
}

// round 12
// speedup vs baseline: 1.5086x; 1.1024x over previous
#include <cuda_runtime.h>
#include <math.h>

// B=1024, T=128, H1=50 (G1=200), H2=150 (G2=600), D2=100
#define B_SZ 1024
#define T_SZ 128

// output: concat of flattened (waveform_feat[1024,20], pef_logits[1024,2],
//                              feat[1024,30], logits[1024,4])
#define OFF_WF   0
#define OFF_PL   20480
#define OFF_FEAT 22528
#define OFF_LG   53248

typedef unsigned long long ull;

static __device__ float  g_out1[(size_t)B_SZ * T_SZ * 100];   // layer1 output (52 MB)
static __device__ float  g_xg2 [(size_t)B_SZ * T_SZ * 600];   // layer2 fwd input proj (315 MB)
static __device__ float2 g_W2p [76 * 600];                    // layer2 fwd Whh, k-pair-major
static __device__ float  g_net [(size_t)B_SZ * 300];          // out2[:, -1]

// ---------------- fast math helpers ----------------
__device__ __forceinline__ float tanh_(float x) {
    float r; asm("tanh.approx.f32 %0, %1;" : "=f"(r) : "f"(x)); return r;
}
__device__ __forceinline__ float sigm(float x) {
    return fmaf(tanh_(0.5f * x), 0.5f, 0.5f);
}
__device__ __forceinline__ float lrelu(float x) { return x > 0.f ? x : 0.3f * x; }

__device__ __forceinline__ ull pack2(float lo, float hi) {
    ull r;
    asm("mov.b64 %0, {%1, %2};" : "=l"(r) : "r"(__float_as_uint(lo)), "r"(__float_as_uint(hi)));
    return r;
}
__device__ __forceinline__ void unpack2(ull v, float& lo, float& hi) {
    unsigned int a, b;
    asm("mov.b64 {%0, %1}, %2;" : "=r"(a), "=r"(b) : "l"(v));
    lo = __uint_as_float(a); hi = __uint_as_float(b);
}
__device__ __forceinline__ void fma2(ull& d, ull a, ull b) {
    asm("fma.rn.f32x2 %0, %1, %2, %3;" : "=l"(d) : "l"(a), "l"(b), "l"(d));
}

// ---------------------------------------------------------------------------
// prep: l2_Whh_f (600x150) -> g_W2p[k2][r] = (W[2k2][r], W[2k2+1][r]), k>=150 -> 0
// ---------------------------------------------------------------------------
__global__ void prep_kernel(const float* __restrict__ Whh2f)
{
    int i = blockIdx.x * 256 + threadIdx.x;
    if (i < 76 * 600) {
        int k2 = i / 600, r = i - k2 * 600;
        float lo = (2 * k2     < 150) ? Whh2f[r * 150 + 2 * k2]     : 0.f;
        float hi = (2 * k2 + 1 < 150) ? Whh2f[r * 150 + 2 * k2 + 1] : 0.f;
        g_W2p[i] = make_float2(lo, hi);
    }
}

// ---------------------------------------------------------------------------
// lstm1: grid (64, 2) = (batch groups of 16, direction), 512 threads.
// Compute phase: 400 threads = (gate row r in 0..199) x (batch half 0/1),
// 8 batches each -> 16 warps/SM for latency hiding (was 8).
// ---------------------------------------------------------------------------
__global__ __launch_bounds__(512) void lstm1_kernel(
    const float* __restrict__ x,
    const float* __restrict__ Wih_f, const float* __restrict__ Whh_f, const float* __restrict__ b_f,
    const float* __restrict__ Wih_b, const float* __restrict__ Whh_b, const float* __restrict__ b_b)
{
    __shared__ __align__(16) float h_s[16 * 52];
    __shared__ float c_s[16 * 50];
    __shared__ float gates_s[16 * 200];
    __shared__ float x_s[16 * 128];

    const int tid = threadIdx.x;
    const int dir = blockIdx.y;
    const int b0  = blockIdx.x * 16;

    const float* Wih = dir ? Wih_b : Wih_f;
    const float* Whh = dir ? Whh_b : Whh_f;
    const float* bb  = dir ? b_b   : b_f;

    for (int i = tid; i < 16 * 128; i += 512) {
        int b = i >> 7, t = i & 127;
        x_s[i] = x[(size_t)(b0 + b) * 128 + t];
    }
    for (int i = tid; i < 16 * 52; i += 512) h_s[i] = 0.f;
    for (int i = tid; i < 16 * 50; i += 512) c_s[i] = 0.f;

    const bool comp = (tid < 400);
    const int r    = comp ? (tid % 200) : 0;      // gate row
    const int bh   = comp ? (tid / 200) * 8 : 0;  // batch base (0 or 8)

    ull w2[26];
    float wih = 0.f, bv = 0.f;
    if (comp) {
#pragma unroll
        for (int k2 = 0; k2 < 26; k2++) {
            float lo = (2 * k2     < 50) ? Whh[r * 50 + 2 * k2]     : 0.f;
            float hi = (2 * k2 + 1 < 50) ? Whh[r * 50 + 2 * k2 + 1] : 0.f;
            w2[k2] = pack2(lo, hi);
        }
        wih = Wih[r];
        bv  = bb[r];
    }
    __syncthreads();

    for (int s = 0; s < T_SZ; s++) {
        const int t = dir ? (127 - s) : s;
        if (comp) {
#pragma unroll 2
            for (int bi = 0; bi < 8; bi++) {
                const int b = bh + bi;
                ull acc = pack2(fmaf(x_s[b * 128 + t], wih, bv), 0.f);
#pragma unroll
                for (int k4 = 0; k4 < 13; k4++) {
                    ulonglong2 hv = *(const ulonglong2*)(h_s + b * 52 + k4 * 4);
                    fma2(acc, hv.x, w2[2 * k4]);
                    fma2(acc, hv.y, w2[2 * k4 + 1]);
                }
                float lo, hi; unpack2(acc, lo, hi);
                gates_s[b * 200 + r] = lo + hi;
            }
        }
        __syncthreads();
        for (int p = tid; p < 16 * 50; p += 512) {
            int b = p / 50, j = p - b * 50;
            float gi = gates_s[b * 200 + j];
            float gf = gates_s[b * 200 + 50 + j];
            float gg = gates_s[b * 200 + 100 + j];
            float go = gates_s[b * 200 + 150 + j];
            float c = sigm(gf) * c_s[b * 50 + j] + sigm(gi) * tanh_(gg);
            c_s[b * 50 + j] = c;
            float h = sigm(go) * tanh_(c);
            h_s[b * 52 + j] = h;
            g_out1[(size_t)(b0 + b) * 12800 + (size_t)t * 100 + dir * 50 + j] = h;
        }
        __syncthreads();
    }
}

// ---------------------------------------------------------------------------
// xg2 GEMM (R7 proven): C[m][g] = out1[m][:100] . Wih2_f[g][:100] + b2_f[g]
// M = 131072, K = 100, N = 600.  BM=64, BN=64, 256 threads, 4x4 tiles, f32x2.
// ---------------------------------------------------------------------------
__global__ __launch_bounds__(256) void xg2_kernel(
    const float* __restrict__ W, const float* __restrict__ bias)
{
    __shared__ __align__(16) float A_s[50 * 68];
    __shared__ __align__(16) float B_s[50 * 68];

    const int m0 = blockIdx.x * 64;
    const int n0 = blockIdx.y * 64;
    const int tid = threadIdx.x;
    const int tx = tid & 15;   // n
    const int ty = tid >> 4;   // m

    ull acc2[8];               // [mi][half], half = n-pair
#pragma unroll
    for (int i = 0; i < 8; i++) acc2[i] = pack2(0.f, 0.f);

    for (int ks = 0; ks < 2; ks++) {
        for (int i = tid; i < 3200; i += 256) {
            int mm = i / 50, kk = i - mm * 50;
            A_s[kk * 68 + mm] = g_out1[(size_t)(m0 + mm) * 100 + ks * 50 + kk];
        }
        for (int i = tid; i < 3200; i += 256) {
            int nn = i / 50, kk = i - nn * 50;
            int g = n0 + nn;
            B_s[kk * 68 + nn] = (g < 600) ? W[g * 100 + ks * 50 + kk] : 0.f;
        }
        __syncthreads();
#pragma unroll 10
        for (int k = 0; k < 50; k++) {
            float4 a = *(const float4*)(A_s + k * 68 + ty * 4);
            ulonglong2 bv = *(const ulonglong2*)(B_s + k * 68 + tx * 4);
            ull ax = pack2(a.x, a.x), ay = pack2(a.y, a.y);
            ull az = pack2(a.z, a.z), aw = pack2(a.w, a.w);
            fma2(acc2[0], ax, bv.x); fma2(acc2[1], ax, bv.y);
            fma2(acc2[2], ay, bv.x); fma2(acc2[3], ay, bv.y);
            fma2(acc2[4], az, bv.x); fma2(acc2[5], az, bv.y);
            fma2(acc2[6], aw, bv.x); fma2(acc2[7], aw, bv.y);
        }
        __syncthreads();
    }

    const int nbase = n0 + tx * 4;
    if (nbase < 600) {
        float4 bb = *(const float4*)(bias + nbase);
#pragma unroll
        for (int mi = 0; mi < 4; mi++) {
            float4 o;
            unpack2(acc2[mi * 2],     o.x, o.y);
            unpack2(acc2[mi * 2 + 1], o.z, o.w);
            o.x += bb.x; o.y += bb.y; o.z += bb.z; o.w += bb.w;
            *(float4*)(g_xg2 + (size_t)(m0 + ty * 4 + mi) * 600 + nbase) = o;
        }
    }
}

// ---------------------------------------------------------------------------
// lstm2 forward recurrence (R7 proven: 38-k2 slab). 128 CTAs x 8 batches,
// 384 threads; threads 0..299 own rows r0=2*tid, r0+1. Streamed k2 38..75
// via depth-4 register prefetch ring; x[t+1] register-prefetched.
// smem floats: Wlo 38*600*2=45600 | gates 8*608=4864 | h 8*152=1216 -> 206720 B
// ---------------------------------------------------------------------------
#define L2_SMEM_BYTES 206720

extern __shared__ float lstm2_sm[];

__global__ __launch_bounds__(384, 1) void lstm2_kernel()
{
    float2* Wlo  = (float2*)lstm2_sm;                 // [k2*600 + r], k2 < 38
    float* gates = lstm2_sm + 45600;                  // [8][608]
    float* h_s   = lstm2_sm + 45600 + 4864;           // [8][152]

    const int tid = threadIdx.x;
    const int b0  = blockIdx.x * 8;
    const bool comp = (tid < 300);
    const int r0 = tid * 2;                           // rows r0, r0+1

    for (int i = tid; i < 11400; i += 384)
        ((float4*)lstm2_sm)[i] = ((const float4*)g_W2p)[i];
    for (int i = tid; i < 8 * 152; i += 384) h_s[i] = 0.f;

    int bs[4], js[4];
    float cs[4];
#pragma unroll
    for (int i = 0; i < 4; i++) {
        int s = tid + i * 384;
        if (s < 1200) { bs[i] = s / 150; js[i] = s - bs[i] * 150; }
        else          { bs[i] = 0;       js[i] = 0; }
        cs[i] = 0.f;
    }

    const float* xbase = g_xg2 + (size_t)b0 * 76800 + r0;   // + b*76800 + t*600

    float2 xp[8];
    if (comp) {
#pragma unroll
        for (int b = 0; b < 8; b++)
            xp[b] = *(const float2*)(xbase + (size_t)b * 76800);
    }
    __syncthreads();

    for (int t = 0; t < T_SZ; t++) {
        if (comp) {
            ull a0[8], a1[8];
#pragma unroll
            for (int b = 0; b < 8; b++) {
                a0[b] = pack2(xp[b].x, 0.f);
                a1[b] = pack2(xp[b].y, 0.f);
            }
            if (t < 127) {
#pragma unroll
                for (int b = 0; b < 8; b++)
                    xp[b] = *(const float2*)(xbase + (size_t)b * 76800 + (t + 1) * 600);
            }

            ulonglong2 wpa[4], wpb[4];
#pragma unroll
            for (int p = 0; p < 4; p++) {
                wpa[p] = __ldg((const ulonglong2*)(g_W2p + (2 * (19 + p))     * 600 + r0));
                wpb[p] = __ldg((const ulonglong2*)(g_W2p + (2 * (19 + p) + 1) * 600 + r0));
            }

#pragma unroll
            for (int it = 0; it < 19; it++) {
                ulonglong2 wA = *(const ulonglong2*)(Wlo + (2 * it)     * 600 + r0);
                ulonglong2 wB = *(const ulonglong2*)(Wlo + (2 * it + 1) * 600 + r0);
#pragma unroll
                for (int b = 0; b < 8; b++) {
                    ulonglong2 hv = *(const ulonglong2*)(h_s + b * 152 + it * 4);
                    fma2(a0[b], hv.x, wA.x);
                    fma2(a0[b], hv.y, wB.x);
                    fma2(a1[b], hv.x, wA.y);
                    fma2(a1[b], hv.y, wB.y);
                }
            }
#pragma unroll
            for (int it = 19; it < 38; it++) {
                const int slot = (it - 19) & 3;
                ulonglong2 wA = wpa[slot];
                ulonglong2 wB = wpb[slot];
                if (it + 4 < 38) {
                    wpa[slot] = __ldg((const ulonglong2*)(g_W2p + (2 * (it + 4))     * 600 + r0));
                    wpb[slot] = __ldg((const ulonglong2*)(g_W2p + (2 * (it + 4) + 1) * 600 + r0));
                }
#pragma unroll
                for (int b = 0; b < 8; b++) {
                    ulonglong2 hv = *(const ulonglong2*)(h_s + b * 152 + it * 4);
                    fma2(a0[b], hv.x, wA.x);
                    fma2(a0[b], hv.y, wB.x);
                    fma2(a1[b], hv.x, wA.y);
                    fma2(a1[b], hv.y, wB.y);
                }
            }

#pragma unroll
            for (int b = 0; b < 8; b++) {
                float l0, h0, l1, h1;
                unpack2(a0[b], l0, h0);
                unpack2(a1[b], l1, h1);
                *(float2*)(gates + b * 608 + r0) = make_float2(l0 + h0, l1 + h1);
            }
        }
        __syncthreads();

#pragma unroll
        for (int i = 0; i < 4; i++) {
            int s = tid + i * 384;
            if (s < 1200) {
                int b = bs[i], j = js[i];
                float gi = gates[b * 608 + j];
                float gf = gates[b * 608 + 150 + j];
                float gg = gates[b * 608 + 300 + j];
                float go = gates[b * 608 + 450 + j];
                float c = sigm(gf) * cs[i] + sigm(gi) * tanh_(gg);
                cs[i] = c;
                float h = sigm(go) * tanh_(c);
                h_s[b * 152 + j] = h;
                if (t == 127) g_net[(size_t)(b0 + b) * 300 + j] = h;
            }
        }
        __syncthreads();
    }
}

// ---------------------------------------------------------------------------
// bwd2: layer2 backward needs only its first step (t = T-1, h0 = c0 = 0).
// ---------------------------------------------------------------------------
__global__ __launch_bounds__(256) void bwd2_kernel(
    const float* __restrict__ Wih2b, const float* __restrict__ b2b)
{
    __shared__ float xv[4 * 100];
    __shared__ float gsm[4 * 600];
    const int tid = threadIdx.x;
    const int b0  = blockIdx.x * 4;

    for (int i = tid; i < 400; i += 256) {
        int b = i / 100, c = i - b * 100;
        xv[i] = g_out1[(size_t)(b0 + b) * 12800 + 127 * 100 + c];
    }
    __syncthreads();

    for (int p = tid; p < 2400; p += 256) {
        int b = p / 600, rr = p - b * 600;
        float acc = b2b[rr];
        const float* Wr = Wih2b + rr * 100;
        const float* xr = xv + b * 100;
#pragma unroll 4
        for (int k = 0; k < 100; k++) acc = fmaf(Wr[k], xr[k], acc);
        gsm[b * 600 + rr] = acc;
    }
    __syncthreads();

    for (int p = tid; p < 600; p += 256) {
        int b = p / 150, j = p - b * 150;
        float gi = gsm[b * 600 + j];
        float gg = gsm[b * 600 + 300 + j];
        float go = gsm[b * 600 + 450 + j];
        float c = sigm(gi) * tanh_(gg);           // c0 = 0 -> forget term vanishes
        float h = sigm(go) * tanh_(c);
        g_net[(size_t)(b0 + b) * 300 + 150 + j] = h;
    }
}

// ---------------------------------------------------------------------------
// heads: one 32-thread block per batch.
// ---------------------------------------------------------------------------
__global__ __launch_bounds__(32) void heads_kernel(
    const float* __restrict__ rrs,
    const float* __restrict__ head_W, const float* __restrict__ head_b,
    const float* __restrict__ pef1_W, const float* __restrict__ pef1_b,
    const float* __restrict__ pef2_W, const float* __restrict__ pef2_b,
    const float* __restrict__ fc_W,   const float* __restrict__ fc_b,
    float* __restrict__ out)
{
    __shared__ float net_s[300];
    __shared__ float feat_s[30];
    __shared__ float rrs_s[4];
    const int b = blockIdx.x;
    const int tid = threadIdx.x;

    for (int i = tid; i < 300; i += 32) net_s[i] = g_net[(size_t)b * 300 + i];
    if (tid < 4) rrs_s[tid] = rrs[b * 4 + tid];
    __syncthreads();

    if (tid < 20) {
        float acc = head_b[tid];
        const float* Wr = head_W + tid * 300;
        for (int k = 0; k < 300; k++) acc = fmaf(Wr[k], net_s[k], acc);
        float v = lrelu(acc);
        feat_s[tid] = v;
        out[OFF_WF + b * 20 + tid] = v;
    } else if (tid < 30) {
        int j = tid - 20;
        float acc = pef1_b[j];
#pragma unroll
        for (int k = 0; k < 4; k++) acc = fmaf(pef1_W[j * 4 + k], rrs_s[k], acc);
        feat_s[20 + j] = lrelu(acc);
    }
    __syncthreads();

    if (tid < 2) {
        float acc = pef2_b[tid];
#pragma unroll
        for (int k = 0; k < 10; k++) acc = fmaf(pef2_W[tid * 10 + k], feat_s[20 + k], acc);
        out[OFF_PL + b * 2 + tid] = acc;
    } else if (tid < 6) {
        int j = tid - 2;
        float acc = fc_b[j];
#pragma unroll
        for (int k = 0; k < 30; k++) acc = fmaf(fc_W[j * 30 + k], feat_s[k], acc);
        out[OFF_LG + b * 4 + j] = acc;
    }
    if (tid < 30) out[OFF_FEAT + b * 30 + tid] = feat_s[tid];
}

// ---------------------------------------------------------------------------
extern "C" void kernel_launch(void* const* d_in, const int* in_sizes, int n_in,
                              void* d_out, int out_size)
{
    const float* x        = (const float*)d_in[0];
    const float* rrs      = (const float*)d_in[1];
    const float* l1_Wih_f = (const float*)d_in[2];
    const float* l1_Whh_f = (const float*)d_in[3];
    const float* l1_b_f   = (const float*)d_in[4];
    const float* l1_Wih_b = (const float*)d_in[5];
    const float* l1_Whh_b = (const float*)d_in[6];
    const float* l1_b_b   = (const float*)d_in[7];
    const float* l2_Wih_f = (const float*)d_in[8];
    const float* l2_Whh_f = (const float*)d_in[9];
    const float* l2_b_f   = (const float*)d_in[10];
    const float* l2_Wih_b = (const float*)d_in[11];
    /* d_in[12] = l2_Whh_b unused (single backward step from h0=0) */
    const float* l2_b_b   = (const float*)d_in[13];
    const float* head_W   = (const float*)d_in[14];
    const float* head_b   = (const float*)d_in[15];
    const float* pef1_W   = (const float*)d_in[16];
    const float* pef1_b   = (const float*)d_in[17];
    const float* pef2_W   = (const float*)d_in[18];
    const float* pef2_b   = (const float*)d_in[19];
    const float* fc_W     = (const float*)d_in[20];
    const float* fc_b     = (const float*)d_in[21];
    float* out = (float*)d_out;

    (void)cudaFuncSetAttribute(lstm2_kernel,
                               cudaFuncAttributeMaxDynamicSharedMemorySize, L2_SMEM_BYTES);

    prep_kernel<<<(76 * 600 + 255) / 256, 256>>>(l2_Whh_f);
    lstm1_kernel<<<dim3(64, 2), 512>>>(x, l1_Wih_f, l1_Whh_f, l1_b_f,
                                          l1_Wih_b, l1_Whh_b, l1_b_b);
    xg2_kernel<<<dim3(2048, 10), 256>>>(l2_Wih_f, l2_b_f);
    lstm2_kernel<<<128, 384, L2_SMEM_BYTES>>>();
    bwd2_kernel<<<256, 256>>>(l2_Wih_b, l2_b_b);
    heads_kernel<<<1024, 32>>>(rrs, head_W, head_b, pef1_W, pef1_b,
                               pef2_W, pef2_b, fc_W, fc_b, out);
}